// round 15
// baseline (speedup 1.0000x reference)
#include <cuda_runtime.h>
#include <cstdint>

#define CTC_V  128
#define NEG2   (-1.0e30f)
#define KS     8                 // time steps per block (== halo depth in lanes)
#define UW     (32 - KS)         // useful lanes per warp (24)
#define NW     6                 // 6 warps x 24 lanes x 2 pairs = 288 >= 257
#define NTHR   (NW * 32)         // 192
#define TMAX   1024
#define BMAX   64
#define TP     (TMAX + KS)       // padded time extent (safe unpredicated prefetch)

// Scratch (padded in t so prefetch never leaves the array).
__device__ float g_probs[TP * BMAX * CTC_V];
__device__ float g_blank[BMAX * TP];

__device__ __forceinline__ float ex2(float x) {
    float y; asm("ex2.approx.ftz.f32 %0, %1;" : "=f"(y) : "f"(x)); return y;
}
__device__ __forceinline__ float lg2(float x) {
    float y; asm("lg2.approx.ftz.f32 %0, %1;" : "=f"(y) : "f"(x)); return y;
}
// Exact renorm: fold R's exponent into M; R -> [1,2). Zero/denorm R safe.
__device__ __forceinline__ void renorm(float& M, float& R) {
    unsigned u = __float_as_uint(R);
    unsigned eb = u >> 23;
    int e = (eb != 0u) ? (int)eb - 127 : 0;
    R = __uint_as_float(u - ((unsigned)e << 23));
    M += (float)e;
}

// ---------------------------------------------------------------------------
// Kernel 1: log2-softmax, 2 rows per warp (interleaved for MLP/ILP).
// ---------------------------------------------------------------------------
__global__ void softmax_k(const float* __restrict__ acts, int rows, int T, int B) {
    int gw   = (blockIdx.x * blockDim.x + threadIdx.x) >> 5;
    int lane = threadIdx.x & 31;
    int r0 = gw * 2;
    if (r0 >= rows) return;
    int r1 = r0 + 1;
    const float L2E = 1.4426950408889634f;
    float4 va = reinterpret_cast<const float4*>(acts)[(size_t)r0 * 32 + lane];
    float4 vb = reinterpret_cast<const float4*>(acts)[(size_t)r1 * 32 + lane];
    float a0 = va.x * L2E, a1 = va.y * L2E, a2 = va.z * L2E, a3 = va.w * L2E;
    float b0 = vb.x * L2E, b1 = vb.y * L2E, b2 = vb.z * L2E, b3 = vb.w * L2E;
    float ma = fmaxf(fmaxf(a0, a1), fmaxf(a2, a3));
    float mb = fmaxf(fmaxf(b0, b1), fmaxf(b2, b3));
#pragma unroll
    for (int o = 16; o; o >>= 1) {
        ma = fmaxf(ma, __shfl_xor_sync(0xffffffffu, ma, o));
        mb = fmaxf(mb, __shfl_xor_sync(0xffffffffu, mb, o));
    }
    float sa = ex2(a0 - ma) + ex2(a1 - ma) + ex2(a2 - ma) + ex2(a3 - ma);
    float sb = ex2(b0 - mb) + ex2(b1 - mb) + ex2(b2 - mb) + ex2(b3 - mb);
#pragma unroll
    for (int o = 16; o; o >>= 1) {
        sa += __shfl_xor_sync(0xffffffffu, sa, o);
        sb += __shfl_xor_sync(0xffffffffu, sb, o);
    }
    float la = lg2(sa) + ma, lb = lg2(sb) + mb;
    reinterpret_cast<float4*>(g_probs)[(size_t)r0 * 32 + lane] =
        make_float4(a0 - la, a1 - la, a2 - la, a3 - la);
    reinterpret_cast<float4*>(g_probs)[(size_t)r1 * 32 + lane] =
        make_float4(b0 - lb, b1 - lb, b2 - lb, b3 - lb);
    if (lane == 0) {
        int t0 = r0 / B, bb0 = r0 - t0 * B;
        int t1 = r1 / B, bb1 = r1 - t1 * B;
        g_blank[bb0 * TP + t0] = a0 - la;
        g_blank[bb1 * TP + t1] = b0 - lb;
    }
}

// ---------------------------------------------------------------------------
// Kernel 2: alpha recursion, (M,R) logsumexp, common-max, TWO PAIRS PER
// THREAD. Pair B (odd) needs only pair A's previous-step registers — no
// shfl; only pair A consumes the cross-lane shfl, so shfl latency is paid
// once per 2 time steps. R12 structure otherwise: one __syncthreads per
// KS-step block, unpredicated full blocks + padded prefetch, fused cost.
// ---------------------------------------------------------------------------
__global__ __launch_bounds__(NTHR, 1) void ctc_alpha_k(
    float* __restrict__ out,
    const int* __restrict__ labels, const int* __restrict__ act_lens,
    const int* __restrict__ label_lens, int T, int B, int L)
{
    __shared__ __align__(16) float4 shA0[2][NW * UW];  // pair A state
    __shared__ __align__(16) float4 shA1[2][NW * UW];  // pair B state
    __shared__ float2 shF[NW * UW * 2];

    const int V = CTC_V;
    const int b = blockIdx.x;
    const int P = L + 1;
    const int PQ = (P + 1) / 2;                     // pair-pair count (129)
    const int tid = threadIdx.x, lane = tid & 31, w = tid >> 5;

    int Tlen = act_lens[b];
    if (Tlen > T) Tlen = T;
    if (Tlen < 1) Tlen = 1;

    const int q  = w * UW + lane - KS;              // pair-pair index
    const int pA = 2 * q, pB = 2 * q + 1;
    const bool in0A = ((unsigned)pA < (unsigned)P);
    const bool in1A = ((unsigned)pA < (unsigned)L);
    const bool in0B = ((unsigned)pB < (unsigned)P);
    const bool in1B = ((unsigned)pB < (unsigned)L);
    const int  labA = in1A ? labels[b * L + pA] : 0;
    const int  labB = in1B ? labels[b * L + pB] : 0;
    const int  prvA = (in1A && pA >= 1) ? labels[b * L + pA - 1] : -1;
    const bool alA  = in1A && (pA >= 1) && (labA != prvA);
    const bool alB  = in1B && (labB != labA);       // pB-1 == pA
    const bool useful = (lane >= KS) && (q < PQ);   // q >= 0 implied

    const float* __restrict__ plA = g_probs + (size_t)b * V + labA;
    const float* __restrict__ plB = g_probs + (size_t)b * V + labB;
    const float* __restrict__ pb  = g_blank + (size_t)b * TP;
    const size_t rstr = (size_t)B * V;

    // ---- t = 0 init ----
    if (useful) {
        float M0A = NEG2, M1A = NEG2;
        if (pA == 0) { M0A = __ldg(pb); if (in1A) M1A = __ldg(plA); }
        shA0[0][q] = make_float4(M0A, 1.0f, M1A, 1.0f);
        shA1[0][q] = make_float4(NEG2, 1.0f, NEG2, 1.0f);   // pB >= 1 at t=0
    }

    // emits for block 0 (t = 1..KS) — unpredicated (padded arrays)
    float eb[KS], eA[KS], eB[KS];
#pragma unroll
    for (int j = 0; j < KS; ++j) {
        int t = 1 + j;
        eb[j] = __ldg(pb + t);
        eA[j] = __ldg(plA + (size_t)t * rstr);
        eB[j] = __ldg(plB + (size_t)t * rstr);
    }
    __syncthreads();

    const int NB     = (Tlen - 1 + KS - 1) / KS;
    const int NBfull = NB > 0 ? NB - 1 : 0;

    float M0A, R0A, M1A, R1A, M0B, R0B, M1B, R1B;

    for (int blk = 0; blk < NB; ++blk) {
        // ---- reload state at time blk*KS (masked) ----
        {
            int qq = (q < 0) ? 0 : (q >= PQ ? PQ - 1 : q);
            float4 vA = shA0[blk & 1][qq];
            float4 vB = shA1[blk & 1][qq];
            bool okq = ((unsigned)q < (unsigned)PQ);
            M0A = (okq && in0A) ? vA.x : NEG2;  R0A = (okq && in0A) ? vA.y : 1.0f;
            M1A = (okq && in1A) ? vA.z : NEG2;  R1A = (okq && in1A) ? vA.w : 1.0f;
            M0B = (okq && in0B) ? vB.x : NEG2;  R0B = (okq && in0B) ? vB.y : 1.0f;
            M1B = (okq && in1B) ? vB.z : NEG2;  R1B = (okq && in1B) ? vB.w : 1.0f;
        }
        // ---- prefetch next block's emits — unpredicated ----
        float nb_[KS], nA_[KS], nB_[KS];
        {
            int tb = (blk + 1) * KS + 1;
#pragma unroll
            for (int j = 0; j < KS; ++j) {
                int t = tb + j;
                nb_[j] = __ldg(pb + t);
                nA_[j] = __ldg(plA + (size_t)t * rstr);
                nB_[j] = __ldg(plB + (size_t)t * rstr);
            }
        }

        if (blk < NBfull) {
            // ---- FULL block: KS steps, unpredicated ----
#pragma unroll
            for (int j = 0; j < KS; ++j) {
                float zM = __shfl_up_sync(0xffffffffu, M1B, 1);
                float zR = __shfl_up_sync(0xffffffffu, R1B, 1);
                // pair B (uses OLD pair A registers; no shfl dependency)
                float mCB = fmaxf(fmaxf(M0B, M1B), M1A);
                float x0b = ex2(M0B - mCB);
                float x1b = ex2(M1B - mCB);
                float xab = ex2(M1A - mCB);
                float RBx = R0B * x0b;
                float RAx = R1A * xab;
                float RAg = alB ? RAx : 0.0f;
                float nR0B = RBx + RAx;
                float nR1B = fmaf(R1B, x1b, RBx + RAg);
                float nM0B = mCB + eb[j];
                float nM1B = mCB + eB[j];
                // pair A (consumes the shfl)
                float mCA = fmaxf(fmaxf(M0A, M1A), zM);
                float x0a = ex2(M0A - mCA);
                float x1a = ex2(M1A - mCA);
                float xza = ex2(zM - mCA);
                float RAx0 = R0A * x0a;
                float Rzx  = zR * xza;
                float Rzg  = alA ? Rzx : 0.0f;
                R0A = RAx0 + Rzx;
                R1A = fmaf(R1A, x1a, RAx0 + Rzg);
                M0A = mCA + eb[j];
                M1A = mCA + eA[j];
                // commit B
                M0B = nM0B; R0B = nR0B; M1B = nM1B; R1B = nR1B;
            }
        } else {
            // ---- TAIL block: same math, predicated commits ----
#pragma unroll
            for (int j = 0; j < KS; ++j) {
                int t = blk * KS + 1 + j;
                float zM = __shfl_up_sync(0xffffffffu, M1B, 1);
                float zR = __shfl_up_sync(0xffffffffu, R1B, 1);
                float mCB = fmaxf(fmaxf(M0B, M1B), M1A);
                float x0b = ex2(M0B - mCB);
                float x1b = ex2(M1B - mCB);
                float xab = ex2(M1A - mCB);
                float RBx = R0B * x0b;
                float RAx = R1A * xab;
                float RAg = alB ? RAx : 0.0f;
                float nR0B = RBx + RAx;
                float nR1B = fmaf(R1B, x1b, RBx + RAg);
                float nM0B = mCB + eb[j];
                float nM1B = mCB + eB[j];
                float mCA = fmaxf(fmaxf(M0A, M1A), zM);
                float x0a = ex2(M0A - mCA);
                float x1a = ex2(M1A - mCA);
                float xza = ex2(zM - mCA);
                float RAx0 = R0A * x0a;
                float Rzx  = zR * xza;
                float Rzg  = alA ? Rzx : 0.0f;
                float nR0A = RAx0 + Rzx;
                float nR1A = fmaf(R1A, x1a, RAx0 + Rzg);
                float nM0A = mCA + eb[j];
                float nM1A = mCA + eA[j];
                bool u = (t < Tlen);
                M0A = (u && in0A) ? nM0A : M0A;  R0A = (u && in0A) ? nR0A : R0A;
                M1A = (u && in1A) ? nM1A : M1A;  R1A = (u && in1A) ? nR1A : R1A;
                M0B = (u && in0B) ? nM0B : M0B;  R0B = (u && in0B) ? nR0B : R0B;
                M1B = (u && in1B) ? nM1B : M1B;  R1B = (u && in1B) ? nR1B : R1B;
            }
        }

        renorm(M0A, R0A); renorm(M1A, R1A);
        renorm(M0B, R0B); renorm(M1B, R1B);

        if (useful) {
            shA0[(blk + 1) & 1][q] = make_float4(M0A, R0A, M1A, R1A);
            shA1[(blk + 1) & 1][q] = make_float4(M0B, R0B, M1B, R1B);
        }
        __syncthreads();

#pragma unroll
        for (int j = 0; j < KS; ++j) { eb[j] = nb_[j]; eA[j] = nA_[j]; eB[j] = nB_[j]; }
    }

    // ---- fused cost ----
    if (useful) {
        float f0A = in0A ? (M0A + lg2(R0A)) : NEG2;
        float f1A = in1A ? (M1A + lg2(R1A)) : NEG2;
        shF[pA] = make_float2(f0A, f1A);
        if (in0B) {
            float f0B = M0B + lg2(R0B);
            float f1B = in1B ? (M1B + lg2(R1B)) : NEG2;
            shF[pB] = make_float2(f0B, f1B);
        }
    }
    __syncthreads();
    if (tid == 0) {
        int e = label_lens[b]; if (e > P - 1) e = P - 1;
        float a0 = shF[e].x;
        float a1 = (e >= 1) ? shF[e - 1].y : NEG2;
        float m = fmaxf(a0, a1);
        float cost = -(m + lg2(ex2(a0 - m) + ex2(a1 - m))) * 0.69314718055994530942f;
        atomicAdd(out, cost);
    }
}

// ---------------------------------------------------------------------------
extern "C" void kernel_launch(void* const* d_in, const int* in_sizes, int n_in,
                              void* d_out, int out_size)
{
    const float* acts      = (const float*)d_in[0];
    const int*   labels    = (const int*)d_in[1];
    const int*   act_lens  = (const int*)d_in[2];
    const int*   label_len = (const int*)d_in[3];

    int B = in_sizes[2];
    int L = in_sizes[1] / B;
    int V = CTC_V;
    int T = in_sizes[0] / (B * V);

    cudaMemsetAsync(d_out, 0, sizeof(float));

    int rows = T * B;
    int nwarp = (rows + 1) / 2;
    softmax_k<<<(nwarp + 7) / 8, 256>>>(acts, rows, T, B);

    ctc_alpha_k<<<B, NTHR>>>((float*)d_out, labels, act_lens, label_len, T, B, L);
}

// round 16
// speedup vs baseline: 1.4069x; 1.4069x over previous
#include <cuda_runtime.h>
#include <cstdint>

#define CTC_V  128
#define NEG2   (-1.0e30f)
#define KS     8                 // time steps per block (== halo depth)
#define UW     (32 - KS)         // useful lanes per warp (24)
#define NW     11
#define NTHR   (NW * 32)         // 352
#define TMAX   1024
#define BMAX   64
#define TP     (TMAX + KS)       // padded time extent
#define PPAD   258

// Scratch (padded in t so forward prefetch never leaves the array).
__device__ float  g_probs[TP * BMAX * CTC_V];
__device__ float  g_blank[BMAX * TP];
__device__ float2 g_alpha[BMAX * PPAD];
__device__ float2 g_beta [BMAX * PPAD];

__device__ __forceinline__ float ex2(float x) {
    float y; asm("ex2.approx.ftz.f32 %0, %1;" : "=f"(y) : "f"(x)); return y;
}
__device__ __forceinline__ float lg2(float x) {
    float y; asm("lg2.approx.ftz.f32 %0, %1;" : "=f"(y) : "f"(x)); return y;
}
// Exact renorm: fold R's exponent into M; R -> [1,2). Zero/denorm R safe.
__device__ __forceinline__ void renorm(float& M, float& R) {
    unsigned u = __float_as_uint(R);
    unsigned eb = u >> 23;
    int e = (eb != 0u) ? (int)eb - 127 : 0;
    R = __uint_as_float(u - ((unsigned)e << 23));
    M += (float)e;
}

// ---------------------------------------------------------------------------
// Kernel 1: log2-softmax, 2 rows per warp.
// ---------------------------------------------------------------------------
__global__ void softmax_k(const float* __restrict__ acts, int rows, int T, int B) {
    int gw   = (blockIdx.x * blockDim.x + threadIdx.x) >> 5;
    int lane = threadIdx.x & 31;
    int r0 = gw * 2;
    if (r0 >= rows) return;
    int r1 = r0 + 1;
    const float L2E = 1.4426950408889634f;
    float4 va = reinterpret_cast<const float4*>(acts)[(size_t)r0 * 32 + lane];
    float4 vb = reinterpret_cast<const float4*>(acts)[(size_t)r1 * 32 + lane];
    float a0 = va.x * L2E, a1 = va.y * L2E, a2 = va.z * L2E, a3 = va.w * L2E;
    float b0 = vb.x * L2E, b1 = vb.y * L2E, b2 = vb.z * L2E, b3 = vb.w * L2E;
    float ma = fmaxf(fmaxf(a0, a1), fmaxf(a2, a3));
    float mb = fmaxf(fmaxf(b0, b1), fmaxf(b2, b3));
#pragma unroll
    for (int o = 16; o; o >>= 1) {
        ma = fmaxf(ma, __shfl_xor_sync(0xffffffffu, ma, o));
        mb = fmaxf(mb, __shfl_xor_sync(0xffffffffu, mb, o));
    }
    float sa = ex2(a0 - ma) + ex2(a1 - ma) + ex2(a2 - ma) + ex2(a3 - ma);
    float sb = ex2(b0 - mb) + ex2(b1 - mb) + ex2(b2 - mb) + ex2(b3 - mb);
#pragma unroll
    for (int o = 16; o; o >>= 1) {
        sa += __shfl_xor_sync(0xffffffffu, sa, o);
        sb += __shfl_xor_sync(0xffffffffu, sb, o);
    }
    float la = lg2(sa) + ma, lb = lg2(sb) + mb;
    reinterpret_cast<float4*>(g_probs)[(size_t)r0 * 32 + lane] =
        make_float4(a0 - la, a1 - la, a2 - la, a3 - la);
    reinterpret_cast<float4*>(g_probs)[(size_t)r1 * 32 + lane] =
        make_float4(b0 - lb, b1 - lb, b2 - lb, b3 - lb);
    if (lane == 0) {
        int t0 = r0 / B, bb0 = r0 - t0 * B;
        int t1 = r1 / B, bb1 = r1 - t1 * B;
        g_blank[bb0 * TP + t0] = a0 - la;
        g_blank[bb1 * TP + t1] = b0 - lb;
    }
}

// ---------------------------------------------------------------------------
// Kernel 2: fused forward+backward alpha/beta recursion. 2 CTAs per batch:
// even CTA = forward (R12 body) to t* = Tlen/2; odd CTA = mirrored backward
// from Tlen-1 down to t*. Both write (M + lg2 R) finals to global.
// ---------------------------------------------------------------------------
__global__ __launch_bounds__(NTHR, 1) void ctc_fb_k(
    const int* __restrict__ labels, const int* __restrict__ act_lens,
    const int* __restrict__ label_lens, int T, int B, int L)
{
    __shared__ __align__(16) float4 shA[2][NW * UW + KS];

    const int V = CTC_V;
    const int cta = blockIdx.x;
    const int b = cta >> 1;
    const bool bwd = (cta & 1);
    const int P = L + 1;
    const int tid = threadIdx.x, lane = tid & 31, w = tid >> 5;

    int Tlen = act_lens[b];
    if (Tlen > T) Tlen = T;
    if (Tlen < 1) Tlen = 1;
    const int tstar = Tlen >> 1;

    const float* __restrict__ pb = g_blank + (size_t)b * TP;
    const size_t rstr = (size_t)B * V;

    if (!bwd) {
        // ================== FORWARD (R12 body, Te = tstar+1) ==================
        const int Te = tstar + 1;
        const int p = w * UW + lane - KS;
        const bool in0 = ((unsigned)p < (unsigned)P);
        const bool in1 = ((unsigned)p < (unsigned)L);
        const int  lab   = in1 ? labels[b * L + p] : 0;
        const bool allow = in1 && (p >= 1) && (lab != labels[b * L + p - 1]);
        const bool useful = (lane >= KS) && in0;
        const float* __restrict__ pl = g_probs + (size_t)b * V + lab;

        float M0 = NEG2, R0 = 1.0f, M1 = NEG2, R1 = 1.0f;
        if (p == 0) { M0 = __ldg(pb); if (in1) M1 = __ldg(pl); }
        if (useful) shA[0][p] = make_float4(M0, R0, M1, R1);

        float eb[KS], el[KS];
#pragma unroll
        for (int j = 0; j < KS; ++j) {
            int t = 1 + j;
            eb[j] = __ldg(pb + t);
            el[j] = __ldg(pl + (size_t)t * rstr);
        }
        __syncthreads();

        const int NB     = (Te - 1 + KS - 1) / KS;
        const int NBfull = NB > 0 ? NB - 1 : 0;

        for (int blk = 0; blk < NB; ++blk) {
            {
                float4 v = in0 ? shA[blk & 1][p] : make_float4(NEG2, 1.f, NEG2, 1.f);
                M0 = v.x; R0 = v.y;
                M1 = in1 ? v.z : NEG2;
                R1 = in1 ? v.w : 1.0f;
            }
            float nb_[KS], nl_[KS];
            {
                int tb = (blk + 1) * KS + 1;
#pragma unroll
                for (int j = 0; j < KS; ++j) {
                    int t = tb + j;                   // padded top: safe
                    nb_[j] = __ldg(pb + t);
                    nl_[j] = __ldg(pl + (size_t)t * rstr);
                }
            }
            if (blk < NBfull) {
#pragma unroll
                for (int j = 0; j < KS; ++j) {
                    float zM = __shfl_up_sync(0xffffffffu, M1, 1);
                    float zR = __shfl_up_sync(0xffffffffu, R1, 1);
                    float mC = fmaxf(fmaxf(M0, M1), zM);
                    float x0 = ex2(M0 - mC);
                    float x1 = ex2(M1 - mC);
                    float xz = ex2(zM - mC);
                    float R0x0 = R0 * x0;
                    float Rzxz = zR * xz;
                    float Rzg  = allow ? Rzxz : 0.0f;
                    R0 = R0x0 + Rzxz;
                    R1 = fmaf(R1, x1, R0x0 + Rzg);
                    M0 = mC + eb[j];
                    M1 = mC + el[j];
                }
            } else {
#pragma unroll
                for (int j = 0; j < KS; ++j) {
                    int t = blk * KS + 1 + j;
                    float zM = __shfl_up_sync(0xffffffffu, M1, 1);
                    float zR = __shfl_up_sync(0xffffffffu, R1, 1);
                    float d   = zM - M0;
                    float x   = ex2(0.0f - fabsf(d));
                    float Mb  = fmaxf(M0, zM);
                    float Rhi = (d > 0.0f) ? zR : R0;
                    float Rlo = (d > 0.0f) ? R0 : zR;
                    float nM0 = Mb + eb[j];
                    float nR0 = fmaf(Rlo, x, Rhi);
                    float Mq  = allow ? zM : NEG2;
                    float m1  = fmaxf(fmaxf(M1, M0), Mq);
                    float nR1 = fmaf(R1, ex2(M1 - m1),
                                fmaf(R0, ex2(M0 - m1), zR * ex2(Mq - m1)));
                    float nM1 = m1 + el[j];
                    bool u = (t < Te);
                    M0 = (u && in0) ? nM0 : M0;  R0 = (u && in0) ? nR0 : R0;
                    M1 = (u && in1) ? nM1 : M1;  R1 = (u && in1) ? nR1 : R1;
                }
            }
            renorm(M0, R0); renorm(M1, R1);
            if (useful) shA[(blk + 1) & 1][p] = make_float4(M0, R0, M1, R1);
            __syncthreads();
#pragma unroll
            for (int j = 0; j < KS; ++j) { eb[j] = nb_[j]; el[j] = nl_[j]; }
        }

        if (useful) {
            float f0 = in0 ? (M0 + lg2(R0)) : NEG2;
            float f1 = in1 ? (M1 + lg2(R1)) : NEG2;
            g_alpha[(size_t)b * PPAD + p] = make_float2(f0, f1);
        }
    } else {
        // ================== BACKWARD (mirrored, beta to t*) ==================
        // beta_t[s] = logadd_{s' in {s, s+1, s+2 if allow[s+2]}} beta_{t+1}[s'] + emit_{t+1}[s']
        // pair q: blank 2q -> {2q, 2q+1} (own pair only);
        //         label 2q+1 -> {2q+1, 2q+2 (next blank), 2q+3 (next label, gated)}
        const int q = w * UW + lane;               // halo = high lanes
        const bool in0 = ((unsigned)q < (unsigned)P);
        const bool in1 = ((unsigned)q < (unsigned)L);
        const int  lab = in1 ? labels[b * L + q] : 0;
        bool allowD = false;
        if (in1 && (q + 1 < L)) allowD = (labels[b * L + q + 1] != lab);
        const bool useful = (lane < UW) && in0;
        const float* __restrict__ pl = g_probs + (size_t)b * V + lab;

        int Lb = label_lens[b];
        if (Lb > L) Lb = L;
        if (Lb < 0) Lb = 0;

        // init at t = Tlen-1: beta = 0 at states {2Lb, 2Lb-1}
        float M0 = (q == Lb)     ? 0.0f : NEG2;  float R0 = 1.0f;
        float M1 = (q == Lb - 1) ? 0.0f : NEG2;  float R1 = 1.0f;
        if (useful) shA[0][q] = make_float4(M0, R0, M1, R1);

        const int ns = Tlen - 1 - tstar;          // backward step count

        // emits for block 0: step k = j uses emit at t = Tlen-1-j
        float eb[KS], el[KS];
#pragma unroll
        for (int j = 0; j < KS; ++j) {
            int te = Tlen - 1 - j; te = te < 0 ? 0 : te;
            eb[j] = __ldg(pb + te);
            el[j] = __ldg(pl + (size_t)te * rstr);
        }
        __syncthreads();

        const int NB     = (ns + KS - 1) / KS;
        const int NBfull = NB > 0 ? NB - 1 : 0;

        for (int blk = 0; blk < NB; ++blk) {
            {
                float4 v = shA[blk & 1][q];        // q in [0, NW*UW+KS) : in bounds
                M0 = in0 ? v.x : NEG2;  R0 = in0 ? v.y : 1.0f;
                M1 = in1 ? v.z : NEG2;  R1 = in1 ? v.w : 1.0f;
            }
            float nb_[KS], nl_[KS];
            {
                int kb = (blk + 1) * KS;
#pragma unroll
                for (int j = 0; j < KS; ++j) {
                    int te = Tlen - 1 - (kb + j); te = te < 0 ? 0 : te;
                    nb_[j] = __ldg(pb + te);
                    nl_[j] = __ldg(pl + (size_t)te * rstr);
                }
            }
            if (blk < NBfull) {
#pragma unroll
                for (int j = 0; j < KS; ++j) {
                    float vb = M0 + eb[j];
                    float vl = M1 + el[j];
                    float db  = __shfl_down_sync(0xffffffffu, vb, 1);
                    float dRb = __shfl_down_sync(0xffffffffu, R0, 1);
                    float dl  = __shfl_down_sync(0xffffffffu, vl, 1);
                    float dRl = __shfl_down_sync(0xffffffffu, R1, 1);
                    float mC = fmaxf(fmaxf(vb, vl), fmaxf(db, dl));
                    float xb  = ex2(vb - mC);
                    float xl  = ex2(vl - mC);
                    float xdb = ex2(db - mC);
                    float xdl = ex2(dl - mC);
                    float tb  = R0 * xb;
                    float t1  = R1 * xl;
                    float tdb = dRb * xdb;
                    float tdl = allowD ? dRl * xdl : 0.0f;
                    R0 = tb + t1;
                    R1 = t1 + tdb + tdl;
                    M0 = mC; M1 = mC;
                }
            } else {
#pragma unroll
                for (int j = 0; j < KS; ++j) {
                    int k = blk * KS + j;
                    float vb = M0 + eb[j];
                    float vl = M1 + el[j];
                    float db  = __shfl_down_sync(0xffffffffu, vb, 1);
                    float dRb = __shfl_down_sync(0xffffffffu, R0, 1);
                    float dl  = __shfl_down_sync(0xffffffffu, vl, 1);
                    float dRl = __shfl_down_sync(0xffffffffu, R1, 1);
                    float mC = fmaxf(fmaxf(vb, vl), fmaxf(db, dl));
                    float xb  = ex2(vb - mC);
                    float xl  = ex2(vl - mC);
                    float xdb = ex2(db - mC);
                    float xdl = ex2(dl - mC);
                    float tb  = R0 * xb;
                    float t1  = R1 * xl;
                    float tdb = dRb * xdb;
                    float tdl = allowD ? dRl * xdl : 0.0f;
                    float nR0 = tb + t1;
                    float nR1 = t1 + tdb + tdl;
                    bool u = (k < ns);
                    M0 = (u && in0) ? mC  : M0;  R0 = (u && in0) ? nR0 : R0;
                    M1 = (u && in1) ? mC  : M1;  R1 = (u && in1) ? nR1 : R1;
                }
            }
            renorm(M0, R0); renorm(M1, R1);
            if (useful) shA[(blk + 1) & 1][q] = make_float4(M0, R0, M1, R1);
            __syncthreads();
#pragma unroll
            for (int j = 0; j < KS; ++j) { eb[j] = nb_[j]; el[j] = nl_[j]; }
        }

        if (useful) {
            float f0 = in0 ? (M0 + lg2(R0)) : NEG2;
            float f1 = in1 ? (M1 + lg2(R1)) : NEG2;
            g_beta[(size_t)b * PPAD + q] = make_float2(f0, f1);
        }
    }
}

// ---------------------------------------------------------------------------
// Kernel 3: combine — loss_b = -ln2 * log2 sum_s 2^(alpha+beta); atomicAdd.
// ---------------------------------------------------------------------------
__global__ void combine_k(float* out, int B, int L) {
    int b = blockIdx.x, lane = threadIdx.x;
    int P = L + 1;
    float m = -3.0e38f, r = 0.0f;
    for (int p = lane; p < P; p += 32) {
        float2 fa = g_alpha[(size_t)b * PPAD + p];
        float2 fb = g_beta [(size_t)b * PPAD + p];
        float v0 = fa.x + fb.x;
        float v1 = fa.y + fb.y;
        float nm = fmaxf(m, v0);
        r = r * ex2(m - nm) + ex2(v0 - nm); m = nm;
        nm = fmaxf(m, v1);
        r = r * ex2(m - nm) + ex2(v1 - nm); m = nm;
    }
#pragma unroll
    for (int o = 16; o; o >>= 1) {
        float om = __shfl_xor_sync(0xffffffffu, m, o);
        float orr = __shfl_xor_sync(0xffffffffu, r, o);
        float nm = fmaxf(m, om);
        r = r * ex2(m - nm) + orr * ex2(om - nm);
        m = nm;
    }
    if (lane == 0)
        atomicAdd(out, -(m + lg2(r)) * 0.69314718055994530942f);
}

// ---------------------------------------------------------------------------
extern "C" void kernel_launch(void* const* d_in, const int* in_sizes, int n_in,
                              void* d_out, int out_size)
{
    const float* acts      = (const float*)d_in[0];
    const int*   labels    = (const int*)d_in[1];
    const int*   act_lens  = (const int*)d_in[2];
    const int*   label_len = (const int*)d_in[3];

    int B = in_sizes[2];
    int L = in_sizes[1] / B;
    int V = CTC_V;
    int T = in_sizes[0] / (B * V);

    cudaMemsetAsync(d_out, 0, sizeof(float));

    int rows = T * B;
    int nwarp = (rows + 1) / 2;
    softmax_k<<<(nwarp + 7) / 8, 256>>>(acts, rows, T, B);

    ctc_fb_k<<<2 * B, NTHR>>>(labels, act_lens, label_len, T, B, L);

    combine_k<<<B, 32>>>((float*)d_out, B, L);
}